// round 10
// baseline (speedup 1.0000x reference)
#include <cuda_runtime.h>
#include <math.h>
#include <stdint.h>

#define PATCH 7
#define PP 49

// Fragment-ordered weight tiles: per (nb, kt): 512 float4 units {h0,h1,l0,l1}
#define BUNITS 512

// Scratch
__device__ float g_act0[1 << 18];    // activations ping (1024*256)
__device__ float g_act1[1 << 18];    // activations pong
__device__ float g_wf[1 << 19];      // 4 layers x fragment-ordered hi/lo weights

__device__ __forceinline__ uint32_t f32_to_tf32(float x) {
    uint32_t r;
    asm("cvt.rna.tf32.f32 %0, %1;" : "=r"(r) : "f"(x));
    return r;
}

__device__ __forceinline__ void mma_tf32(float* c, const uint32_t* a, uint32_t b0, uint32_t b1) {
    asm volatile(
        "mma.sync.aligned.m16n8k8.row.col.f32.tf32.tf32.f32 "
        "{%0,%1,%2,%3}, {%4,%5,%6,%7}, {%8,%9}, {%0,%1,%2,%3};\n"
        : "+f"(c[0]), "+f"(c[1]), "+f"(c[2]), "+f"(c[3])
        : "r"(a[0]), "r"(a[1]), "r"(a[2]), "r"(a[3]), "r"(b0), "r"(b1));
}

__device__ __forceinline__ void cp_async16(void* smem_dst, const void* gmem_src) {
    uint32_t s = (uint32_t)__cvta_generic_to_shared(smem_dst);
    asm volatile("cp.async.ca.shared.global [%0], [%1], 16;\n" :: "r"(s), "l"(gmem_src));
}
__device__ __forceinline__ void cp_async_commit() {
    asm volatile("cp.async.commit_group;\n");
}
__device__ __forceinline__ void cp_async_wait0() {
    asm volatile("cp.async.wait_group 0;\n");
}

// ---------------------------------------------------------------------------
// prep_w: decompose W (4 layers, [K=256][N=256]) into tf32 hi/lo, fragment
// order: Wf[layer][nb(8)][kt(8)][unit(512)] float4 {h0,h1,l0,l1},
// unit = (kf*4+nf)*32 + lane; lane=(g,tg):
//   h0/l0 from W[kt*32+kf*8+tg   ][nb*32+nf*8+g]
//   h1/l1 from W[kt*32+kf*8+tg+4 ][nb*32+nf*8+g]
// ---------------------------------------------------------------------------
__global__ void __launch_bounds__(256)
prep_w_kernel(const float* __restrict__ W0, const float* __restrict__ W1,
              const float* __restrict__ W2, const float* __restrict__ W3,
              float* __restrict__ Wf, int N) {
    __shared__ float tile[32][33];
    const int bid = blockIdx.x;
    const int layer = bid >> 6;
    const int nb = (bid >> 3) & 7;
    const int kt = bid & 7;
    const float* W = (layer == 0) ? W0 : (layer == 1) ? W1 : (layer == 2) ? W2 : W3;

    const int tid = threadIdx.x;
    {
        const int r = tid >> 3;
        const int c4 = (tid & 7) * 4;
        float4 w = *reinterpret_cast<const float4*>(&W[(size_t)(kt * 32 + r) * N + nb * 32 + c4]);
        tile[r][c4 + 0] = w.x;
        tile[r][c4 + 1] = w.y;
        tile[r][c4 + 2] = w.z;
        tile[r][c4 + 3] = w.w;
    }
    __syncthreads();

    float4* out = reinterpret_cast<float4*>(Wf) + (size_t)bid * BUNITS;
#pragma unroll
    for (int i = 0; i < 2; i++) {
        const int o = tid + i * 256;
        const int kf = o >> 7;
        const int nf = (o >> 5) & 3;
        const int lane = o & 31;
        const int g = lane >> 2;
        const int tg = lane & 3;
        const float w0 = tile[kf * 8 + tg][nf * 8 + g];
        const float w1 = tile[kf * 8 + tg + 4][nf * 8 + g];
        const float h0 = __uint_as_float(f32_to_tf32(w0));
        const float h1 = __uint_as_float(f32_to_tf32(w1));
        const float l0 = __uint_as_float(f32_to_tf32(w0 - h0));
        const float l1 = __uint_as_float(f32_to_tf32(w1 - h1));
        out[o] = make_float4(h0, h1, l0, l1);
    }
}

// ---------------------------------------------------------------------------
// 3xTF32 warp-split-K GEMM + bias (+ReLU): C = A @ W + b
// Block: 256 threads (8 warps), output 16x32. Warp (ks = wid&1, nf = wid>>1)
// computes the m16n8 tile `nf` over k-half `ks`; epilogue reduces the halves
// via smem. Per iteration: 2 k-tiles of 32 (one per k-half), double-buffered.
// A: raw LDG -> (compute) -> cvt+STS (fragment order). B: cp.async of
// pre-fragmented Wf. All fragment reads: 1x LDS.128, conflict-free.
// ---------------------------------------------------------------------------
template <bool RELU>
__global__ void __launch_bounds__(256)
gemm_frag_kernel(const float* __restrict__ A, const float* __restrict__ Wf,
                 const float* __restrict__ bias, float* __restrict__ C,
                 int M, int N, int K) {
    __shared__ float4 Ahi[2][256];
    __shared__ float4 Alo[2][256];
    __shared__ float4 Bf[2][1024];

    const int tid = threadIdx.x;
    const int lane = tid & 31;
    const int wid = tid >> 5;
    const int wks = wid & 1;        // k-half
    const int wnf = wid >> 1;       // n8 tile (0..3)
    const int g = lane >> 2;
    const int tg = lane & 3;

    const int bm = blockIdx.y * 16;
    const int bn = blockIdx.x * 32;
    const int ktiles = K / 32;           // 8
    const int iters = ktiles / 2;        // 4

    // A staging map: unit = tid = kh*128 + kf*32 + lane'
    const int s_kh = tid >> 7;
    const int s_kf = (tid >> 5) & 3;
    const int s_g = lane >> 2;
    const int s_tg = lane & 3;
    const size_t a_rowoff = (size_t)(bm + s_g) * K;

    const float4* wf_base = reinterpret_cast<const float4*>(Wf) + (size_t)blockIdx.x * ktiles * BUNITS;

    float x0, x1, x2, x3;

    auto ldgA = [&](int t) {
        const int kc = (t + s_kh * (iters)) * 32 + s_kf * 8 + s_tg;
        const float* p = &A[a_rowoff + kc];
        x0 = p[0];
        x1 = p[(size_t)8 * K];
        x2 = p[4];
        x3 = p[(size_t)8 * K + 4];
    };
    auto cvtA = [&](int buf) {
        const float h0 = __uint_as_float(f32_to_tf32(x0));
        const float h1 = __uint_as_float(f32_to_tf32(x1));
        const float h2 = __uint_as_float(f32_to_tf32(x2));
        const float h3 = __uint_as_float(f32_to_tf32(x3));
        Ahi[buf][tid] = make_float4(h0, h1, h2, h3);
        Alo[buf][tid] = make_float4(__uint_as_float(f32_to_tf32(x0 - h0)),
                                    __uint_as_float(f32_to_tf32(x1 - h1)),
                                    __uint_as_float(f32_to_tf32(x2 - h2)),
                                    __uint_as_float(f32_to_tf32(x3 - h3)));
    };
    auto cpB = [&](int t, int buf) {
#pragma unroll
        for (int j = 0; j < 4; j++) {
            const int u = tid + j * 256;
            const int kh = u >> 9;
            const int uw = u & 511;
            cp_async16(&Bf[buf][u], wf_base + (size_t)(t + kh * iters) * BUNITS + uw);
        }
        cp_async_commit();
    };

    // prologue
    ldgA(0);
    cpB(0, 0);
    cvtA(0);
    cp_async_wait0();
    __syncthreads();

    float acc[4] = {0.f, 0.f, 0.f, 0.f};
    int cur = 0;

    for (int t = 0; t < iters; t++) {
        if (t + 1 < iters) {
            ldgA(t + 1);
            cpB(t + 1, cur ^ 1);
        }

#pragma unroll
        for (int kf = 0; kf < 4; kf++) {
            const float4 ah = Ahi[cur][wks * 128 + kf * 32 + lane];
            const float4 al = Alo[cur][wks * 128 + kf * 32 + lane];
            const float4 bv = Bf[cur][wks * 512 + (kf * 4 + wnf) * 32 + lane];
            uint32_t ahi[4] = {__float_as_uint(ah.x), __float_as_uint(ah.y),
                               __float_as_uint(ah.z), __float_as_uint(ah.w)};
            uint32_t alo[4] = {__float_as_uint(al.x), __float_as_uint(al.y),
                               __float_as_uint(al.z), __float_as_uint(al.w)};
            const uint32_t bh0 = __float_as_uint(bv.x);
            const uint32_t bh1 = __float_as_uint(bv.y);
            const uint32_t bl0 = __float_as_uint(bv.z);
            const uint32_t bl1 = __float_as_uint(bv.w);
            mma_tf32(acc, ahi, bh0, bh1);
            mma_tf32(acc, ahi, bl0, bl1);
            mma_tf32(acc, alo, bh0, bh1);
        }

        if (t + 1 < iters) {
            cvtA(cur ^ 1);
            cp_async_wait0();
            __syncthreads();
            cur ^= 1;
        }
    }

    // Epilogue: reduce the two k-halves via smem (reuse Ahi)
    __syncthreads();
    float4* red = &Ahi[0][0];
    red[wid * 32 + lane] = make_float4(acc[0], acc[1], acc[2], acc[3]);
    __syncthreads();

    if (wks == 0) {
        const float4 o = red[wid * 32 + lane];
        const float4 p = red[(wid + 1) * 32 + lane];
        const int col = bn + wnf * 8 + 2 * tg;
        const int row0 = bm + g;
        const float b0 = bias[col];
        const float b1 = bias[col + 1];
        float v0 = o.x + p.x + b0;
        float v1 = o.y + p.y + b1;
        float v2 = o.z + p.z + b0;
        float v3 = o.w + p.w + b1;
        if (RELU) {
            v0 = fmaxf(v0, 0.f);
            v1 = fmaxf(v1, 0.f);
            v2 = fmaxf(v2, 0.f);
            v3 = fmaxf(v3, 0.f);
        }
        *reinterpret_cast<float2*>(&C[(size_t)row0 * N + col]) = make_float2(v0, v1);
        *reinterpret_cast<float2*>(&C[(size_t)(row0 + 8) * N + col]) = make_float2(v2, v3);
    }
}

// ---------------------------------------------------------------------------
// Patch gather + dot + indices. One block (256 threads) per query.
// Output layout in d_out (float32):
//   [0, N*49)        logits (n, py, px)
//   [N*49, N*49*5)   indices as float (n, py, px, {b,y,x,q})
// ---------------------------------------------------------------------------
__global__ void __launch_bounds__(256)
patch_kernel(const float* __restrict__ fm, const float* __restrict__ qe,
             const float* __restrict__ qpos, const int* __restrict__ shapes,
             float* __restrict__ out, int N, int Q, int D) {
    __shared__ float sq[256];
    const int n = blockIdx.x;
    if (n >= N) return;

    const int b = n / Q;
    const int q = n - b * Q;
    const int Hb = shapes[2 * b + 0];
    const int Wb = shapes[2 * b + 1];

    const float posx = qpos[2 * n + 0];
    const float posy = qpos[2 * n + 1];
    const int cy = (int)(posy * (float)Hb);
    const int cx = (int)(posx * (float)Wb);

    for (int d = threadIdx.x; d < D; d += blockDim.x)
        sq[d] = qe[(size_t)n * D + d];
    __syncthreads();

    const int warp = threadIdx.x >> 5;
    const int lane = threadIdx.x & 31;
    const float4* sq4 = reinterpret_cast<const float4*>(sq);
    const float4 q0 = sq4[lane];
    const float4 q1 = sq4[lane + 32];

    float* out_logits = out;
    float* out_idx = out + (size_t)N * PP;

    for (int p = warp; p < PP; p += 8) {
        const int dy = p / PATCH - PATCH / 2;
        const int dx = p % PATCH - PATCH / 2;
        int y = cy + dy;
        int x = cx + dx;
        y = min(max(y, 0), Hb - 1);
        x = min(max(x, 0), Wb - 1);

        const size_t row_off = (((size_t)b * Hb + y) * Wb + x) * (size_t)D;
        const float4* row = reinterpret_cast<const float4*>(fm + row_off);

        const float4 f0 = row[lane];
        const float4 f1 = row[lane + 32];

        float s = f0.x * q0.x + f0.y * q0.y + f0.z * q0.z + f0.w * q0.w;
        s = fmaf(f1.x, q1.x, s);
        s = fmaf(f1.y, q1.y, s);
        s = fmaf(f1.z, q1.z, s);
        s = fmaf(f1.w, q1.w, s);

#pragma unroll
        for (int off = 16; off; off >>= 1)
            s += __shfl_xor_sync(0xFFFFFFFFu, s, off);

        if (lane == 0) {
            out_logits[(size_t)n * PP + p] = s;
            float4 iv = make_float4((float)b, (float)y, (float)x, (float)q);
            *reinterpret_cast<float4*>(&out_idx[((size_t)n * PP + p) * 4]) = iv;
        }
    }
}

extern "C" void kernel_launch(void* const* d_in, const int* in_sizes, int n_in,
                              void* d_out, int out_size) {
    const float* fm      = (const float*)d_in[0];
    const float* queries = (const float*)d_in[1];
    const float* qpos    = (const float*)d_in[2];
    const int*   shapes  = (const int*)d_in[4];
    const float* W0 = (const float*)d_in[5];
    const float* b0 = (const float*)d_in[6];
    const float* W1 = (const float*)d_in[7];
    const float* b1 = (const float*)d_in[8];
    const float* W2 = (const float*)d_in[9];
    const float* b2 = (const float*)d_in[10];
    const float* W3 = (const float*)d_in[11];
    const float* b3 = (const float*)d_in[12];

    const int B = in_sizes[3];               // query_batch_offsets length
    const int D = in_sizes[6];               // bias length (256)
    const int N = in_sizes[1] / D;           // total queries (1024)
    const int Q = N / B;
    const int LSZ = (D / 32) * (D / 32) * BUNITS * 4;   // floats per layer in Wf

    float* act0;
    float* act1;
    float* wf;
    cudaGetSymbolAddress((void**)&act0, g_act0);
    cudaGetSymbolAddress((void**)&act1, g_act1);
    cudaGetSymbolAddress((void**)&wf, g_wf);

    prep_w_kernel<<<4 * (D / 32) * (D / 32), 256>>>(W0, W1, W2, W3, wf, D);

    dim3 gblock(256);
    dim3 ggrid(D / 32, N / 16);              // (8, 64) = 512 blocks

    gemm_frag_kernel<true ><<<ggrid, gblock>>>(queries, wf + 0 * LSZ, b0, act0, N, D, D);
    gemm_frag_kernel<true ><<<ggrid, gblock>>>(act0,    wf + 1 * LSZ, b1, act1, N, D, D);
    gemm_frag_kernel<true ><<<ggrid, gblock>>>(act1,    wf + 2 * LSZ, b2, act0, N, D, D);
    gemm_frag_kernel<false><<<ggrid, gblock>>>(act0,    wf + 3 * LSZ, b3, act1, N, D, D);

    patch_kernel<<<N, 256>>>(fm, act1, qpos, shapes, (float*)d_out, N, Q, D);
}

// round 11
// speedup vs baseline: 1.2489x; 1.2489x over previous
#include <cuda_runtime.h>
#include <math.h>
#include <stdint.h>

#define PATCH 7
#define PP 49

// Scratch
__device__ float g_act0[1 << 18];    // activations ping (1024*256)
__device__ float g_act1[1 << 18];    // activations pong
__device__ float g_wf[1 << 19];      // 4 layers x nf-paired fragment hi/lo weights (2 MB)

__device__ __forceinline__ uint32_t f32_to_tf32(float x) {
    uint32_t r;
    asm("cvt.rna.tf32.f32 %0, %1;" : "=r"(r) : "f"(x));
    return r;
}

__device__ __forceinline__ void mma_tf32(float* c, const uint32_t* a, uint32_t b0, uint32_t b1) {
    asm volatile(
        "mma.sync.aligned.m16n8k8.row.col.f32.tf32.tf32.f32 "
        "{%0,%1,%2,%3}, {%4,%5,%6,%7}, {%8,%9}, {%0,%1,%2,%3};\n"
        : "+f"(c[0]), "+f"(c[1]), "+f"(c[2]), "+f"(c[3])
        : "r"(a[0]), "r"(a[1]), "r"(a[2]), "r"(a[3]), "r"(b0), "r"(b1));
}

__device__ __forceinline__ void cp_async16(void* smem_dst, const void* gmem_src) {
    uint32_t s = (uint32_t)__cvta_generic_to_shared(smem_dst);
    asm volatile("cp.async.ca.shared.global [%0], [%1], 16;\n" :: "r"(s), "l"(gmem_src));
}
__device__ __forceinline__ void cp_async_commit() {
    asm volatile("cp.async.commit_group;\n");
}
__device__ __forceinline__ void cp_async_wait0() {
    asm volatile("cp.async.wait_group 0;\n");
}

// ---------------------------------------------------------------------------
// prep_w: decompose W (4 layers, [K=256][N=256]) into tf32 hi/lo, nf-PAIRED
// fragment order. Linear float4 layout per layer:
//   u = ((nb*32 + k8)*2 + nfp)*64 + hl*32 + lane
// BH unit (hl=0) = {h0_nf0, h1_nf0, h0_nf1, h1_nf1}, BL (hl=1) = lo parts,
// where for nfl in {0,1}: nf = nfp*2+nfl, n = nb*32 + nf*8 + g,
//   b0 = W[k8*8+tg][n], b1 = W[k8*8+tg+4][n],  lane = g*4+tg.
// 65536 threads: one per (layer, nb, k8, nfp, lane).
// ---------------------------------------------------------------------------
__global__ void __launch_bounds__(256)
prep_w_kernel(const float* __restrict__ W0, const float* __restrict__ W1,
              const float* __restrict__ W2, const float* __restrict__ W3,
              float* __restrict__ Wf, int N) {
    const int t = blockIdx.x * blockDim.x + threadIdx.x;   // 0..65535
    const int lane = t & 31;
    const int nfp = (t >> 5) & 1;
    const int k8 = (t >> 6) & 31;
    const int nb = (t >> 11) & 7;
    const int layer = t >> 14;
    const float* W = (layer == 0) ? W0 : (layer == 1) ? W1 : (layer == 2) ? W2 : W3;

    const int g = lane >> 2;
    const int tg = lane & 3;

    float h[4], l[4];
#pragma unroll
    for (int nfl = 0; nfl < 2; nfl++) {
        const int n = nb * 32 + (nfp * 2 + nfl) * 8 + g;
        const float w0 = W[(size_t)(k8 * 8 + tg) * N + n];
        const float w1 = W[(size_t)(k8 * 8 + tg + 4) * N + n];
        h[nfl * 2 + 0] = __uint_as_float(f32_to_tf32(w0));
        h[nfl * 2 + 1] = __uint_as_float(f32_to_tf32(w1));
        l[nfl * 2 + 0] = __uint_as_float(f32_to_tf32(w0 - h[nfl * 2 + 0]));
        l[nfl * 2 + 1] = __uint_as_float(f32_to_tf32(w1 - h[nfl * 2 + 1]));
    }
    // per-layer linear index (layer folded in by t's high bits)
    float4* out = reinterpret_cast<float4*>(Wf);
    const int base = (t >> 5) * 64;         // ((layer*8+nb)*32 + k8)*2 + nfp, times 64
    out[base + lane]      = make_float4(h[0], h[1], h[2], h[3]);
    out[base + 32 + lane] = make_float4(l[0], l[1], l[2], l[3]);
}

// ---------------------------------------------------------------------------
// 3xTF32 GEMM + bias (+ReLU), warp tile m32n16, 4-way warp split-K.
// Block: 256 threads (8 warps: ks = wid&3, nfp = wid>>2), output 32x32.
// Iter = 64-k slab (8 k8 steps); warp ks handles k8l = ks*2, ks*2+1.
// Per k8-step: 6 LDS.128 (ah0,al0,ah1,al1,BH,BL) -> 12 MMA into 4 acc sets.
// A: scalar-gather + cvt into single-buffered fragment smem (16KB).
// B: contiguous cp.async of nf-paired pre-fragmented weights (2x16KB).
// Epilogue: 4-way split-K reduction via smem (reuses A region).
// ---------------------------------------------------------------------------
template <bool RELU>
__global__ void __launch_bounds__(256)
gemm_tf32_kernel(const float* __restrict__ A, const float* __restrict__ WfL,
                 const float* __restrict__ bias, float* __restrict__ C,
                 int M, int N, int K) {
    __shared__ float4 pool[3072];           // 48 KB
    float4* Ah = pool;                      // 512 units (8 KB)
    float4* Al = pool + 512;                // 512 units (8 KB)
    float4* Bf = pool + 1024;               // 2 x 1024 units (2 x 16 KB)

    const int tid = threadIdx.x;
    const int lane = tid & 31;
    const int wid = tid >> 5;
    const int wks = wid & 3;
    const int wnfp = wid >> 2;
    const int g = lane >> 2;
    const int tg = lane & 3;

    const int bm = blockIdx.y * 32;
    const int bn = blockIdx.x * 32;
    const int iters = K >> 6;               // 4

    // --- A staging: this thread owns units su0 = tid, su1 = tid + 256 ---
    // su: k8l = su>>6, mi = (su>>5)&1, lane' = su&31
    int s_k8l[2], s_mi[2];
    {
        s_k8l[0] = tid >> 6;           s_mi[0] = (tid >> 5) & 1;
        const int su1 = tid + 256;
        s_k8l[1] = su1 >> 6;           s_mi[1] = (su1 >> 5) & 1;
    }
    float xr[2][4];

    auto ldgA = [&](int t) {
#pragma unroll
        for (int i = 0; i < 2; i++) {
            const int kc = t * 64 + s_k8l[i] * 8 + tg;
            const int r0 = bm + s_mi[i] * 16 + g;
            const float* p = &A[(size_t)r0 * K + kc];
            xr[i][0] = p[0];
            xr[i][1] = p[(size_t)8 * K];
            xr[i][2] = p[4];
            xr[i][3] = p[(size_t)8 * K + 4];
        }
    };
    auto cvtA = [&]() {
#pragma unroll
        for (int i = 0; i < 2; i++) {
            const float h0 = __uint_as_float(f32_to_tf32(xr[i][0]));
            const float h1 = __uint_as_float(f32_to_tf32(xr[i][1]));
            const float h2 = __uint_as_float(f32_to_tf32(xr[i][2]));
            const float h3 = __uint_as_float(f32_to_tf32(xr[i][3]));
            const int su = tid + i * 256;
            Ah[su] = make_float4(h0, h1, h2, h3);
            Al[su] = make_float4(__uint_as_float(f32_to_tf32(xr[i][0] - h0)),
                                 __uint_as_float(f32_to_tf32(xr[i][1] - h1)),
                                 __uint_as_float(f32_to_tf32(xr[i][2] - h2)),
                                 __uint_as_float(f32_to_tf32(xr[i][3] - h3)));
        }
    };

    // B source: per-layer Wf + this nb strip; iter t slab = 1024 contiguous f4
    const float4* wf_nb = reinterpret_cast<const float4*>(WfL) + (size_t)blockIdx.x * 4096;
    auto cpB = [&](int t, int buf) {
        const float4* src = wf_nb + (size_t)t * 1024;
        float4* dst = Bf + buf * 1024;
#pragma unroll
        for (int j = 0; j < 4; j++)
            cp_async16(&dst[tid + j * 256], &src[tid + j * 256]);
        cp_async_commit();
    };

    // prologue
    ldgA(0);
    cpB(0, 0);
    cvtA();
    cp_async_wait0();
    __syncthreads();

    float acc[2][2][4];
#pragma unroll
    for (int mi = 0; mi < 2; mi++)
#pragma unroll
        for (int nfl = 0; nfl < 2; nfl++)
#pragma unroll
            for (int i = 0; i < 4; i++) acc[mi][nfl][i] = 0.f;

    int cur = 0;
    for (int t = 0; t < iters; t++) {
        if (t + 1 < iters) {
            ldgA(t + 1);
            cpB(t + 1, cur ^ 1);
        }

        const float4* bcur = Bf + cur * 1024;
#pragma unroll
        for (int s = 0; s < 2; s++) {
            const int k8l = wks * 2 + s;
            const float4 bh = bcur[k8l * 128 + wnfp * 64 + lane];
            const float4 bl = bcur[k8l * 128 + wnfp * 64 + 32 + lane];
            const uint32_t bh0 = __float_as_uint(bh.x), bh1 = __float_as_uint(bh.y);
            const uint32_t bh2 = __float_as_uint(bh.z), bh3 = __float_as_uint(bh.w);
            const uint32_t bl0 = __float_as_uint(bl.x), bl1 = __float_as_uint(bl.y);
            const uint32_t bl2 = __float_as_uint(bl.z), bl3 = __float_as_uint(bl.w);
#pragma unroll
            for (int mi = 0; mi < 2; mi++) {
                const float4 ahv = Ah[k8l * 64 + mi * 32 + lane];
                const float4 alv = Al[k8l * 64 + mi * 32 + lane];
                uint32_t ahi[4] = {__float_as_uint(ahv.x), __float_as_uint(ahv.y),
                                   __float_as_uint(ahv.z), __float_as_uint(ahv.w)};
                uint32_t alo[4] = {__float_as_uint(alv.x), __float_as_uint(alv.y),
                                   __float_as_uint(alv.z), __float_as_uint(alv.w)};
                mma_tf32(acc[mi][0], ahi, bh0, bh1);
                mma_tf32(acc[mi][1], ahi, bh2, bh3);
                mma_tf32(acc[mi][0], ahi, bl0, bl1);
                mma_tf32(acc[mi][1], ahi, bl2, bl3);
                mma_tf32(acc[mi][0], alo, bh0, bh1);
                mma_tf32(acc[mi][1], alo, bh2, bh3);
            }
        }

        if (t + 1 < iters) {
            __syncthreads();        // all warps done reading A smem
            cvtA();                 // overwrite A (single buffer)
            cp_async_wait0();       // B(t+1) landed
            __syncthreads();
            cur ^= 1;
        }
    }

    // Epilogue: 4-way split-K reduction via smem (reuse A region = pool[0..1023])
    __syncthreads();
    float4* red = pool;
#pragma unroll
    for (int mi = 0; mi < 2; mi++)
#pragma unroll
        for (int nfl = 0; nfl < 2; nfl++)
            red[wid * 128 + (mi * 2 + nfl) * 32 + lane] =
                make_float4(acc[mi][nfl][0], acc[mi][nfl][1], acc[mi][nfl][2], acc[mi][nfl][3]);
    __syncthreads();

    // reducer: warp w handles (mi = w&1, nfg = w>>1)
    {
        const int mi = wid & 1;
        const int nfg = wid >> 1;
        const int nfp = nfg >> 1;
        const int nfl = nfg & 1;
        const int set = mi * 2 + nfl;
        float4 s0 = red[(nfp * 4 + 0) * 128 + set * 32 + lane];
        const float4 s1 = red[(nfp * 4 + 1) * 128 + set * 32 + lane];
        const float4 s2 = red[(nfp * 4 + 2) * 128 + set * 32 + lane];
        const float4 s3 = red[(nfp * 4 + 3) * 128 + set * 32 + lane];
        s0.x = (s0.x + s1.x) + (s2.x + s3.x);
        s0.y = (s0.y + s1.y) + (s2.y + s3.y);
        s0.z = (s0.z + s1.z) + (s2.z + s3.z);
        s0.w = (s0.w + s1.w) + (s2.w + s3.w);

        const int col = bn + nfg * 8 + 2 * tg;
        const int row0 = bm + mi * 16 + g;
        const float b0 = bias[col];
        const float b1 = bias[col + 1];
        float v0 = s0.x + b0, v1 = s0.y + b1, v2 = s0.z + b0, v3 = s0.w + b1;
        if (RELU) {
            v0 = fmaxf(v0, 0.f);
            v1 = fmaxf(v1, 0.f);
            v2 = fmaxf(v2, 0.f);
            v3 = fmaxf(v3, 0.f);
        }
        *reinterpret_cast<float2*>(&C[(size_t)row0 * N + col]) = make_float2(v0, v1);
        *reinterpret_cast<float2*>(&C[(size_t)(row0 + 8) * N + col]) = make_float2(v2, v3);
    }
}

// ---------------------------------------------------------------------------
// Patch gather + dot + indices. One block (256 threads) per query.
// Output layout in d_out (float32):
//   [0, N*49)        logits (n, py, px)
//   [N*49, N*49*5)   indices as float (n, py, px, {b,y,x,q})
// ---------------------------------------------------------------------------
__global__ void __launch_bounds__(256)
patch_kernel(const float* __restrict__ fm, const float* __restrict__ qe,
             const float* __restrict__ qpos, const int* __restrict__ shapes,
             float* __restrict__ out, int N, int Q, int D) {
    __shared__ float sq[256];
    const int n = blockIdx.x;
    if (n >= N) return;

    const int b = n / Q;
    const int q = n - b * Q;
    const int Hb = shapes[2 * b + 0];
    const int Wb = shapes[2 * b + 1];

    const float posx = qpos[2 * n + 0];
    const float posy = qpos[2 * n + 1];
    const int cy = (int)(posy * (float)Hb);
    const int cx = (int)(posx * (float)Wb);

    for (int d = threadIdx.x; d < D; d += blockDim.x)
        sq[d] = qe[(size_t)n * D + d];
    __syncthreads();

    const int warp = threadIdx.x >> 5;
    const int lane = threadIdx.x & 31;
    const float4* sq4 = reinterpret_cast<const float4*>(sq);
    const float4 q0 = sq4[lane];
    const float4 q1 = sq4[lane + 32];

    float* out_logits = out;
    float* out_idx = out + (size_t)N * PP;

    for (int p = warp; p < PP; p += 8) {
        const int dy = p / PATCH - PATCH / 2;
        const int dx = p % PATCH - PATCH / 2;
        int y = cy + dy;
        int x = cx + dx;
        y = min(max(y, 0), Hb - 1);
        x = min(max(x, 0), Wb - 1);

        const size_t row_off = (((size_t)b * Hb + y) * Wb + x) * (size_t)D;
        const float4* row = reinterpret_cast<const float4*>(fm + row_off);

        const float4 f0 = row[lane];
        const float4 f1 = row[lane + 32];

        float s = f0.x * q0.x + f0.y * q0.y + f0.z * q0.z + f0.w * q0.w;
        s = fmaf(f1.x, q1.x, s);
        s = fmaf(f1.y, q1.y, s);
        s = fmaf(f1.z, q1.z, s);
        s = fmaf(f1.w, q1.w, s);

#pragma unroll
        for (int off = 16; off; off >>= 1)
            s += __shfl_xor_sync(0xFFFFFFFFu, s, off);

        if (lane == 0) {
            out_logits[(size_t)n * PP + p] = s;
            float4 iv = make_float4((float)b, (float)y, (float)x, (float)q);
            *reinterpret_cast<float4*>(&out_idx[((size_t)n * PP + p) * 4]) = iv;
        }
    }
}

extern "C" void kernel_launch(void* const* d_in, const int* in_sizes, int n_in,
                              void* d_out, int out_size) {
    const float* fm      = (const float*)d_in[0];
    const float* queries = (const float*)d_in[1];
    const float* qpos    = (const float*)d_in[2];
    const int*   shapes  = (const int*)d_in[4];
    const float* W0 = (const float*)d_in[5];
    const float* b0 = (const float*)d_in[6];
    const float* W1 = (const float*)d_in[7];
    const float* b1 = (const float*)d_in[8];
    const float* W2 = (const float*)d_in[9];
    const float* b2 = (const float*)d_in[10];
    const float* W3 = (const float*)d_in[11];
    const float* b3 = (const float*)d_in[12];

    const int B = in_sizes[3];               // query_batch_offsets length
    const int D = in_sizes[6];               // bias length (256)
    const int N = in_sizes[1] / D;           // total queries (1024)
    const int Q = N / B;
    const int LSZ = 8 * 4096 * 4;            // floats per layer in Wf (131072)

    float* act0;
    float* act1;
    float* wf;
    cudaGetSymbolAddress((void**)&act0, g_act0);
    cudaGetSymbolAddress((void**)&act1, g_act1);
    cudaGetSymbolAddress((void**)&wf, g_wf);

    prep_w_kernel<<<256, 256>>>(W0, W1, W2, W3, wf, D);

    dim3 gblock(256);
    dim3 ggrid(D / 32, N / 32);              // (8, 32) = 256 blocks

    gemm_tf32_kernel<true ><<<ggrid, gblock>>>(queries, wf + 0 * LSZ, b0, act0, N, D, D);
    gemm_tf32_kernel<true ><<<ggrid, gblock>>>(act0,    wf + 1 * LSZ, b1, act1, N, D, D);
    gemm_tf32_kernel<true ><<<ggrid, gblock>>>(act1,    wf + 2 * LSZ, b2, act0, N, D, D);
    gemm_tf32_kernel<false><<<ggrid, gblock>>>(act0,    wf + 3 * LSZ, b3, act1, N, D, D);

    patch_kernel<<<N, 256>>>(fm, act1, qpos, shapes, (float*)d_out, N, Q, D);
}

// round 12
// speedup vs baseline: 1.3825x; 1.1069x over previous
#include <cuda_runtime.h>
#include <math.h>
#include <stdint.h>

#define PATCH 7
#define PP 49

// Scratch: fragment-ordered hi/lo activation buffers (ping/pong), plain final
// activations, and fragment-ordered hi/lo weights.
__device__ float g_fhA[1 << 18];
__device__ float g_flA[1 << 18];
__device__ float g_fhB[1 << 18];
__device__ float g_flB[1 << 18];
__device__ float g_act[1 << 18];
__device__ float g_wf[1 << 19];

__device__ __forceinline__ uint32_t f32_to_tf32(float x) {
    uint32_t r;
    asm("cvt.rna.tf32.f32 %0, %1;" : "=r"(r) : "f"(x));
    return r;
}

__device__ __forceinline__ void mma_tf32(float* c, const uint32_t* a, uint32_t b0, uint32_t b1) {
    asm volatile(
        "mma.sync.aligned.m16n8k8.row.col.f32.tf32.tf32.f32 "
        "{%0,%1,%2,%3}, {%4,%5,%6,%7}, {%8,%9}, {%0,%1,%2,%3};\n"
        : "+f"(c[0]), "+f"(c[1]), "+f"(c[2]), "+f"(c[3])
        : "r"(a[0]), "r"(a[1]), "r"(a[2]), "r"(a[3]), "r"(b0), "r"(b1));
}

__device__ __forceinline__ void cp_async16(void* smem_dst, const void* gmem_src) {
    uint32_t s = (uint32_t)__cvta_generic_to_shared(smem_dst);
    asm volatile("cp.async.ca.shared.global [%0], [%1], 16;\n" :: "r"(s), "l"(gmem_src));
}
__device__ __forceinline__ void cp_async_commit() {
    asm volatile("cp.async.commit_group;\n");
}
__device__ __forceinline__ void cp_async_wait0() {
    asm volatile("cp.async.wait_group 0;\n");
}

// ---------------------------------------------------------------------------
// prep: blocks [0,256): weights -> nf-paired fragment hi/lo (same as R11):
//   Wf f4 index: ((nb*32 + k8)*2 + nfp)*64 + hl*32 + lane
// blocks [256,512): queries -> fragment hi/lo activations:
//   act f4 index: (mb*8 + t8)*256 + su, su = k8l*64 + mi*32 + lane, where
//   f4 = {x(r,c), x(r+8,c), x(r,c+4), x(r+8,c+4)},
//   r = mb*32 + mi*16 + g, c = t8*32 + k8l*8 + tg, lane = g*4 + tg.
// ---------------------------------------------------------------------------
__global__ void __launch_bounds__(256)
prep_kernel(const float* __restrict__ W0, const float* __restrict__ W1,
            const float* __restrict__ W2, const float* __restrict__ W3,
            const float* __restrict__ Qin,
            float* __restrict__ Wf, float* __restrict__ aHi, float* __restrict__ aLo,
            int N) {
    if (blockIdx.x < 256) {
        const int t = blockIdx.x * blockDim.x + threadIdx.x;   // 0..65535
        const int lane = t & 31;
        const int nfp = (t >> 5) & 1;
        const int k8 = (t >> 6) & 31;
        const int nb = (t >> 11) & 7;
        const int layer = t >> 14;
        const float* W = (layer == 0) ? W0 : (layer == 1) ? W1 : (layer == 2) ? W2 : W3;
        const int g = lane >> 2;
        const int tg = lane & 3;

        float h[4], l[4];
#pragma unroll
        for (int nfl = 0; nfl < 2; nfl++) {
            const int n = nb * 32 + (nfp * 2 + nfl) * 8 + g;
            const float w0 = W[(size_t)(k8 * 8 + tg) * N + n];
            const float w1 = W[(size_t)(k8 * 8 + tg + 4) * N + n];
            h[nfl * 2 + 0] = __uint_as_float(f32_to_tf32(w0));
            h[nfl * 2 + 1] = __uint_as_float(f32_to_tf32(w1));
            l[nfl * 2 + 0] = __uint_as_float(f32_to_tf32(w0 - h[nfl * 2 + 0]));
            l[nfl * 2 + 1] = __uint_as_float(f32_to_tf32(w1 - h[nfl * 2 + 1]));
        }
        float4* out = reinterpret_cast<float4*>(Wf);
        const int base = (t >> 5) * 64;
        out[base + lane]      = make_float4(h[0], h[1], h[2], h[3]);
        out[base + 32 + lane] = make_float4(l[0], l[1], l[2], l[3]);
    } else {
        const int id = (blockIdx.x - 256) * blockDim.x + threadIdx.x;  // 0..65535
        const int su = id & 255;
        const int t8 = (id >> 8) & 7;
        const int mb = id >> 11;
        const int k8l = su >> 6;
        const int mi = (su >> 5) & 1;
        const int lane = su & 31;
        const int g = lane >> 2;
        const int tg = lane & 3;
        const int r = mb * 32 + mi * 16 + g;
        const int c = t8 * 32 + k8l * 8 + tg;
        const float x0 = Qin[(size_t)r * N + c];
        const float x1 = Qin[(size_t)(r + 8) * N + c];
        const float x2 = Qin[(size_t)r * N + c + 4];
        const float x3 = Qin[(size_t)(r + 8) * N + c + 4];
        const float h0 = __uint_as_float(f32_to_tf32(x0));
        const float h1 = __uint_as_float(f32_to_tf32(x1));
        const float h2 = __uint_as_float(f32_to_tf32(x2));
        const float h3 = __uint_as_float(f32_to_tf32(x3));
        reinterpret_cast<float4*>(aHi)[id] = make_float4(h0, h1, h2, h3);
        reinterpret_cast<float4*>(aLo)[id] =
            make_float4(__uint_as_float(f32_to_tf32(x0 - h0)),
                        __uint_as_float(f32_to_tf32(x1 - h1)),
                        __uint_as_float(f32_to_tf32(x2 - h2)),
                        __uint_as_float(f32_to_tf32(x3 - h3)));
    }
}

// ---------------------------------------------------------------------------
// 3xTF32 GEMM, fragment-in / fragment-out. Block 256 thr (8 warps:
// wks = wid&3 selects the k8 step of each 32-k slab, wnfp = wid>>2), output
// 32x32. 8 iters of BK=32, everything double-buffered cp.async.
// Mainloop per warp per iter: 4 cp.async + 6 LDS.128 + 12 MMA + 1 sync.
// Epilogue: 4-way split-K smem reduction + bias (+ReLU), then either
// fragment-order hi/lo output (FRAGOUT) or plain row-major C.
// ---------------------------------------------------------------------------
template <bool RELU, bool FRAGOUT>
__global__ void __launch_bounds__(256)
gemm_tf32_kernel(const float* __restrict__ aHi, const float* __restrict__ aLo,
                 const float* __restrict__ WfL, const float* __restrict__ bias,
                 float* __restrict__ oHi, float* __restrict__ oLo,
                 float* __restrict__ Cplain, int M, int N, int K) {
    __shared__ float4 pool[2048];           // 32 KB
    float4* AhS = pool;                     // [2][256]
    float4* AlS = pool + 512;               // [2][256]
    float4* BfS = pool + 1024;              // [2][512]

    const int tid = threadIdx.x;
    const int lane = tid & 31;
    const int wid = tid >> 5;
    const int wks = wid & 3;
    const int wnfp = wid >> 2;
    const int g = lane >> 2;
    const int tg = lane & 3;

    const int mb = blockIdx.y;
    const int bn = blockIdx.x * 32;
    const int iters = K >> 5;               // 8

    const float4* aHi4 = reinterpret_cast<const float4*>(aHi);
    const float4* aLo4 = reinterpret_cast<const float4*>(aLo);
    const float4* wf_nb = reinterpret_cast<const float4*>(WfL) + (size_t)blockIdx.x * 4096;

    auto stage = [&](int t, int buf) {
        const size_t ao = (size_t)(mb * 8 + t) * 256 + tid;
        cp_async16(&AhS[buf * 256 + tid], &aHi4[ao]);
        cp_async16(&AlS[buf * 256 + tid], &aLo4[ao]);
        const float4* bsrc = wf_nb + (size_t)t * 512;
        cp_async16(&BfS[buf * 512 + tid], &bsrc[tid]);
        cp_async16(&BfS[buf * 512 + tid + 256], &bsrc[tid + 256]);
        cp_async_commit();
    };

    stage(0, 0);
    cp_async_wait0();
    __syncthreads();

    float acc[2][2][4];
#pragma unroll
    for (int mi = 0; mi < 2; mi++)
#pragma unroll
        for (int nfl = 0; nfl < 2; nfl++)
#pragma unroll
            for (int i = 0; i < 4; i++) acc[mi][nfl][i] = 0.f;

    int cur = 0;
    for (int t = 0; t < iters; t++) {
        if (t + 1 < iters) stage(t + 1, cur ^ 1);

        const float4 bh = BfS[cur * 512 + wks * 128 + wnfp * 64 + lane];
        const float4 bl = BfS[cur * 512 + wks * 128 + wnfp * 64 + 32 + lane];
        const uint32_t bh0 = __float_as_uint(bh.x), bh1 = __float_as_uint(bh.y);
        const uint32_t bh2 = __float_as_uint(bh.z), bh3 = __float_as_uint(bh.w);
        const uint32_t bl0 = __float_as_uint(bl.x), bl1 = __float_as_uint(bl.y);
        const uint32_t bl2 = __float_as_uint(bl.z), bl3 = __float_as_uint(bl.w);
#pragma unroll
        for (int mi = 0; mi < 2; mi++) {
            const float4 ahv = AhS[cur * 256 + wks * 64 + mi * 32 + lane];
            const float4 alv = AlS[cur * 256 + wks * 64 + mi * 32 + lane];
            uint32_t ahi[4] = {__float_as_uint(ahv.x), __float_as_uint(ahv.y),
                               __float_as_uint(ahv.z), __float_as_uint(ahv.w)};
            uint32_t alo[4] = {__float_as_uint(alv.x), __float_as_uint(alv.y),
                               __float_as_uint(alv.z), __float_as_uint(alv.w)};
            mma_tf32(acc[mi][0], ahi, bh0, bh1);
            mma_tf32(acc[mi][1], ahi, bh2, bh3);
            mma_tf32(acc[mi][0], ahi, bl0, bl1);
            mma_tf32(acc[mi][1], ahi, bl2, bl3);
            mma_tf32(acc[mi][0], alo, bh0, bh1);
            mma_tf32(acc[mi][1], alo, bh2, bh3);
        }

        if (t + 1 < iters) {
            cp_async_wait0();
            __syncthreads();
            cur ^= 1;
        }
    }

    // ---- split-K reduction via smem (pool[0..1023]) ----
    __syncthreads();
    float4* red = pool;
#pragma unroll
    for (int mi = 0; mi < 2; mi++)
#pragma unroll
        for (int nfl = 0; nfl < 2; nfl++)
            red[wid * 128 + (mi * 2 + nfl) * 32 + lane] =
                make_float4(acc[mi][nfl][0], acc[mi][nfl][1], acc[mi][nfl][2], acc[mi][nfl][3]);
    __syncthreads();

    // every warp is a reducer: (mi = wid&1, nfg = wid>>1)
    const int mi = wid & 1;
    const int nfg = wid >> 1;
    const int nfp = nfg >> 1;
    const int nfl = nfg & 1;
    const int set = mi * 2 + nfl;
    float4 s0 = red[(nfp * 4 + 0) * 128 + set * 32 + lane];
    const float4 s1 = red[(nfp * 4 + 1) * 128 + set * 32 + lane];
    const float4 s2 = red[(nfp * 4 + 2) * 128 + set * 32 + lane];
    const float4 s3 = red[(nfp * 4 + 3) * 128 + set * 32 + lane];
    float v[4];
    v[0] = (s0.x + s1.x) + (s2.x + s3.x);
    v[1] = (s0.y + s1.y) + (s2.y + s3.y);
    v[2] = (s0.z + s1.z) + (s2.z + s3.z);
    v[3] = (s0.w + s1.w) + (s2.w + s3.w);

    const int col = bn + nfg * 8 + 2 * tg;
    const float b0v = bias[col];
    const float b1v = bias[col + 1];
    v[0] += b0v; v[1] += b1v; v[2] += b0v; v[3] += b1v;
    if (RELU) {
#pragma unroll
        for (int e = 0; e < 4; e++) v[e] = fmaxf(v[e], 0.f);
    }

    if (FRAGOUT) {
        // stage decomposed values in fragment order, then contiguous copy out
        float* stHi = reinterpret_cast<float*>(pool + 1024);   // 256 f4
        float* stLo = stHi + 1024;                             // 256 f4
#pragma unroll
        for (int e = 0; e < 4; e++) {
            const int cc = 2 * tg + (e & 1);                   // col offset in n8
            const int lane_c = g * 4 + (cc & 3);
            const int comp = (e >> 1) + 2 * (cc >> 2);
            const int su = nfg * 64 + mi * 32 + lane_c;
            const float hi = __uint_as_float(f32_to_tf32(v[e]));
            stHi[su * 4 + comp] = hi;
            stLo[su * 4 + comp] = __uint_as_float(f32_to_tf32(v[e] - hi));
        }
        __syncthreads();
        const size_t dst = (size_t)(mb * 8 + blockIdx.x) * 256 + tid;
        reinterpret_cast<float4*>(oHi)[dst] = reinterpret_cast<float4*>(stHi)[tid];
        reinterpret_cast<float4*>(oLo)[dst] = reinterpret_cast<float4*>(stLo)[tid];
    } else {
        const int row0 = mb * 32 + mi * 16 + g;
        *reinterpret_cast<float2*>(&Cplain[(size_t)row0 * N + col]) = make_float2(v[0], v[1]);
        *reinterpret_cast<float2*>(&Cplain[(size_t)(row0 + 8) * N + col]) = make_float2(v[2], v[3]);
    }
}

// ---------------------------------------------------------------------------
// Patch gather + dot + indices. One block (256 threads) per query.
// Output layout in d_out (float32):
//   [0, N*49)        logits (n, py, px)
//   [N*49, N*49*5)   indices as float (n, py, px, {b,y,x,q})
// ---------------------------------------------------------------------------
__global__ void __launch_bounds__(256)
patch_kernel(const float* __restrict__ fm, const float* __restrict__ qe,
             const float* __restrict__ qpos, const int* __restrict__ shapes,
             float* __restrict__ out, int N, int Q, int D) {
    __shared__ float sq[256];
    const int n = blockIdx.x;
    if (n >= N) return;

    const int b = n / Q;
    const int q = n - b * Q;
    const int Hb = shapes[2 * b + 0];
    const int Wb = shapes[2 * b + 1];

    const float posx = qpos[2 * n + 0];
    const float posy = qpos[2 * n + 1];
    const int cy = (int)(posy * (float)Hb);
    const int cx = (int)(posx * (float)Wb);

    for (int d = threadIdx.x; d < D; d += blockDim.x)
        sq[d] = qe[(size_t)n * D + d];
    __syncthreads();

    const int warp = threadIdx.x >> 5;
    const int lane = threadIdx.x & 31;
    const float4* sq4 = reinterpret_cast<const float4*>(sq);
    const float4 q0 = sq4[lane];
    const float4 q1 = sq4[lane + 32];

    float* out_logits = out;
    float* out_idx = out + (size_t)N * PP;

    for (int p = warp; p < PP; p += 8) {
        const int dy = p / PATCH - PATCH / 2;
        const int dx = p % PATCH - PATCH / 2;
        int y = cy + dy;
        int x = cx + dx;
        y = min(max(y, 0), Hb - 1);
        x = min(max(x, 0), Wb - 1);

        const size_t row_off = (((size_t)b * Hb + y) * Wb + x) * (size_t)D;
        const float4* row = reinterpret_cast<const float4*>(fm + row_off);

        const float4 f0 = row[lane];
        const float4 f1 = row[lane + 32];

        float s = f0.x * q0.x + f0.y * q0.y + f0.z * q0.z + f0.w * q0.w;
        s = fmaf(f1.x, q1.x, s);
        s = fmaf(f1.y, q1.y, s);
        s = fmaf(f1.z, q1.z, s);
        s = fmaf(f1.w, q1.w, s);

#pragma unroll
        for (int off = 16; off; off >>= 1)
            s += __shfl_xor_sync(0xFFFFFFFFu, s, off);

        if (lane == 0) {
            out_logits[(size_t)n * PP + p] = s;
            float4 iv = make_float4((float)b, (float)y, (float)x, (float)q);
            *reinterpret_cast<float4*>(&out_idx[((size_t)n * PP + p) * 4]) = iv;
        }
    }
}

extern "C" void kernel_launch(void* const* d_in, const int* in_sizes, int n_in,
                              void* d_out, int out_size) {
    const float* fm      = (const float*)d_in[0];
    const float* queries = (const float*)d_in[1];
    const float* qpos    = (const float*)d_in[2];
    const int*   shapes  = (const int*)d_in[4];
    const float* W0 = (const float*)d_in[5];
    const float* b0 = (const float*)d_in[6];
    const float* W1 = (const float*)d_in[7];
    const float* b1 = (const float*)d_in[8];
    const float* W2 = (const float*)d_in[9];
    const float* b2 = (const float*)d_in[10];
    const float* W3 = (const float*)d_in[11];
    const float* b3 = (const float*)d_in[12];

    const int B = in_sizes[3];               // query_batch_offsets length
    const int D = in_sizes[6];               // bias length (256)
    const int N = in_sizes[1] / D;           // total queries (1024)
    const int Q = N / B;
    const int LSZ = 8 * 4096 * 4;            // floats per layer in Wf

    float *fhA, *flA, *fhB, *flB, *act, *wf;
    cudaGetSymbolAddress((void**)&fhA, g_fhA);
    cudaGetSymbolAddress((void**)&flA, g_flA);
    cudaGetSymbolAddress((void**)&fhB, g_fhB);
    cudaGetSymbolAddress((void**)&flB, g_flB);
    cudaGetSymbolAddress((void**)&act, g_act);
    cudaGetSymbolAddress((void**)&wf, g_wf);

    prep_kernel<<<512, 256>>>(W0, W1, W2, W3, queries, wf, fhA, flA, D);

    dim3 gblock(256);
    dim3 ggrid(D / 32, N / 32);              // (8, 32) = 256 blocks

    gemm_tf32_kernel<true,  true ><<<ggrid, gblock>>>(fhA, flA, wf + 0 * LSZ, b0, fhB, flB, nullptr, N, D, D);
    gemm_tf32_kernel<true,  true ><<<ggrid, gblock>>>(fhB, flB, wf + 1 * LSZ, b1, fhA, flA, nullptr, N, D, D);
    gemm_tf32_kernel<true,  true ><<<ggrid, gblock>>>(fhA, flA, wf + 2 * LSZ, b2, fhB, flB, nullptr, N, D, D);
    gemm_tf32_kernel<false, false><<<ggrid, gblock>>>(fhB, flB, wf + 3 * LSZ, b3, nullptr, nullptr, act, N, D, D);

    patch_kernel<<<N, 256>>>(fm, act, qpos, shapes, (float*)d_out, N, Q, D);
}

// round 13
// speedup vs baseline: 1.4528x; 1.0509x over previous
#include <cuda_runtime.h>
#include <math.h>
#include <stdint.h>

#define PATCH 7
#define PP 49

// Scratch: fragment-ordered hi/lo activation buffers (ping/pong), plain final
// activations, and fragment-ordered hi/lo weights.
__device__ float g_fhA[1 << 18];
__device__ float g_flA[1 << 18];
__device__ float g_fhB[1 << 18];
__device__ float g_flB[1 << 18];
__device__ float g_act[1 << 18];
__device__ float g_wf[1 << 19];

__device__ __forceinline__ uint32_t f32_to_tf32(float x) {
    uint32_t r;
    asm("cvt.rna.tf32.f32 %0, %1;" : "=r"(r) : "f"(x));
    return r;
}

__device__ __forceinline__ void mma_tf32(float* c, const uint32_t* a, uint32_t b0, uint32_t b1) {
    asm volatile(
        "mma.sync.aligned.m16n8k8.row.col.f32.tf32.tf32.f32 "
        "{%0,%1,%2,%3}, {%4,%5,%6,%7}, {%8,%9}, {%0,%1,%2,%3};\n"
        : "+f"(c[0]), "+f"(c[1]), "+f"(c[2]), "+f"(c[3])
        : "r"(a[0]), "r"(a[1]), "r"(a[2]), "r"(a[3]), "r"(b0), "r"(b1));
}

__device__ __forceinline__ void cp_async16(void* smem_dst, const void* gmem_src) {
    uint32_t s = (uint32_t)__cvta_generic_to_shared(smem_dst);
    asm volatile("cp.async.ca.shared.global [%0], [%1], 16;\n" :: "r"(s), "l"(gmem_src));
}
__device__ __forceinline__ void cp_async_commit() {
    asm volatile("cp.async.commit_group;\n");
}
__device__ __forceinline__ void cp_async_wait1() {
    asm volatile("cp.async.wait_group 1;\n");
}
__device__ __forceinline__ void cp_async_wait0() {
    asm volatile("cp.async.wait_group 0;\n");
}

// ---------------------------------------------------------------------------
// prep: blocks [0,256): weights -> nf-paired fragment hi/lo:
//   Wf f4 index: ((nb*32 + k8)*2 + nfp)*64 + hl*32 + lane
// blocks [256,512): queries -> fragment hi/lo activations:
//   act f4 index: (mb*8 + t8)*256 + su, su = k8l*64 + mi*32 + lane, where
//   f4 = {x(r,c), x(r+8,c), x(r,c+4), x(r+8,c+4)},
//   r = mb*32 + mi*16 + g, c = t8*32 + k8l*8 + tg, lane = g*4 + tg.
// ---------------------------------------------------------------------------
__global__ void __launch_bounds__(256)
prep_kernel(const float* __restrict__ W0, const float* __restrict__ W1,
            const float* __restrict__ W2, const float* __restrict__ W3,
            const float* __restrict__ Qin,
            float* __restrict__ Wf, float* __restrict__ aHi, float* __restrict__ aLo,
            int N) {
    if (blockIdx.x < 256) {
        const int t = blockIdx.x * blockDim.x + threadIdx.x;   // 0..65535
        const int lane = t & 31;
        const int nfp = (t >> 5) & 1;
        const int k8 = (t >> 6) & 31;
        const int nb = (t >> 11) & 7;
        const int layer = t >> 14;
        const float* W = (layer == 0) ? W0 : (layer == 1) ? W1 : (layer == 2) ? W2 : W3;
        const int g = lane >> 2;
        const int tg = lane & 3;

        float h[4], l[4];
#pragma unroll
        for (int nfl = 0; nfl < 2; nfl++) {
            const int n = nb * 32 + (nfp * 2 + nfl) * 8 + g;
            const float w0 = W[(size_t)(k8 * 8 + tg) * N + n];
            const float w1 = W[(size_t)(k8 * 8 + tg + 4) * N + n];
            h[nfl * 2 + 0] = __uint_as_float(f32_to_tf32(w0));
            h[nfl * 2 + 1] = __uint_as_float(f32_to_tf32(w1));
            l[nfl * 2 + 0] = __uint_as_float(f32_to_tf32(w0 - h[nfl * 2 + 0]));
            l[nfl * 2 + 1] = __uint_as_float(f32_to_tf32(w1 - h[nfl * 2 + 1]));
        }
        float4* out = reinterpret_cast<float4*>(Wf);
        const int base = (t >> 5) * 64;
        out[base + lane]      = make_float4(h[0], h[1], h[2], h[3]);
        out[base + 32 + lane] = make_float4(l[0], l[1], l[2], l[3]);
    } else {
        const int id = (blockIdx.x - 256) * blockDim.x + threadIdx.x;  // 0..65535
        const int su = id & 255;
        const int t8 = (id >> 8) & 7;
        const int mb = id >> 11;
        const int k8l = su >> 6;
        const int mi = (su >> 5) & 1;
        const int lane = su & 31;
        const int g = lane >> 2;
        const int tg = lane & 3;
        const int r = mb * 32 + mi * 16 + g;
        const int c = t8 * 32 + k8l * 8 + tg;
        const float x0 = Qin[(size_t)r * N + c];
        const float x1 = Qin[(size_t)(r + 8) * N + c];
        const float x2 = Qin[(size_t)r * N + c + 4];
        const float x3 = Qin[(size_t)(r + 8) * N + c + 4];
        const float h0 = __uint_as_float(f32_to_tf32(x0));
        const float h1 = __uint_as_float(f32_to_tf32(x1));
        const float h2 = __uint_as_float(f32_to_tf32(x2));
        const float h3 = __uint_as_float(f32_to_tf32(x3));
        reinterpret_cast<float4*>(aHi)[id] = make_float4(h0, h1, h2, h3);
        reinterpret_cast<float4*>(aLo)[id] =
            make_float4(__uint_as_float(f32_to_tf32(x0 - h0)),
                        __uint_as_float(f32_to_tf32(x1 - h1)),
                        __uint_as_float(f32_to_tf32(x2 - h2)),
                        __uint_as_float(f32_to_tf32(x3 - h3)));
    }
}

// ---------------------------------------------------------------------------
// 3xTF32 GEMM, fragment-in / fragment-out, 3-stage cp.async pipeline.
// Block 256 thr (8 warps: wks = wid&3, wnfp = wid>>2), output 32x32.
// 8 iters of BK=32; data for iter t prefetched 2 iters ahead (wait_group 1).
// Stage s layout in pool: [s*1024 .. ): Ah[256], Al[256], B[512] (f4 units).
// Epilogue: 4-way split-K smem reduction + bias (+ReLU), then either
// fragment-order hi/lo output (FRAGOUT) or plain row-major C.
// ---------------------------------------------------------------------------
template <bool RELU, bool FRAGOUT>
__global__ void __launch_bounds__(256)
gemm_tf32_kernel(const float* __restrict__ aHi, const float* __restrict__ aLo,
                 const float* __restrict__ WfL, const float* __restrict__ bias,
                 float* __restrict__ oHi, float* __restrict__ oLo,
                 float* __restrict__ Cplain, int M, int N, int K) {
    __shared__ float4 pool[3072];           // 48 KB = 3 stages x 16 KB

    const int tid = threadIdx.x;
    const int lane = tid & 31;
    const int wid = tid >> 5;
    const int wks = wid & 3;
    const int wnfp = wid >> 2;
    const int g = lane >> 2;
    const int tg = lane & 3;

    const int mb = blockIdx.y;
    const int bn = blockIdx.x * 32;
    const int iters = K >> 5;               // 8

    const float4* aHi4 = reinterpret_cast<const float4*>(aHi);
    const float4* aLo4 = reinterpret_cast<const float4*>(aLo);
    const float4* wf_nb = reinterpret_cast<const float4*>(WfL) + (size_t)blockIdx.x * 4096;

    auto stage = [&](int t, int s) {
        float4* dst = pool + s * 1024;
        const size_t ao = (size_t)(mb * 8 + t) * 256 + tid;
        cp_async16(&dst[tid], &aHi4[ao]);
        cp_async16(&dst[256 + tid], &aLo4[ao]);
        const float4* bsrc = wf_nb + (size_t)t * 512;
        cp_async16(&dst[512 + tid], &bsrc[tid]);
        cp_async16(&dst[768 + tid], &bsrc[tid + 256]);
        cp_async_commit();
    };

    // prologue: 2 stages in flight
    stage(0, 0);
    stage(1, 1);

    float acc[2][2][4];
#pragma unroll
    for (int mi = 0; mi < 2; mi++)
#pragma unroll
        for (int nfl = 0; nfl < 2; nfl++)
#pragma unroll
            for (int i = 0; i < 4; i++) acc[mi][nfl][i] = 0.f;

    int s = 0;
    for (int t = 0; t < iters; t++) {
        if (t + 2 < iters) cp_async_wait1();
        else               cp_async_wait0();
        __syncthreads();
        if (t + 2 < iters) stage(t + 2, (s + 2) % 3);

        const float4* base = pool + s * 1024;
        const float4 bh = base[512 + wks * 128 + wnfp * 64 + lane];
        const float4 bl = base[512 + wks * 128 + wnfp * 64 + 32 + lane];
        const uint32_t bh0 = __float_as_uint(bh.x), bh1 = __float_as_uint(bh.y);
        const uint32_t bh2 = __float_as_uint(bh.z), bh3 = __float_as_uint(bh.w);
        const uint32_t bl0 = __float_as_uint(bl.x), bl1 = __float_as_uint(bl.y);
        const uint32_t bl2 = __float_as_uint(bl.z), bl3 = __float_as_uint(bl.w);
#pragma unroll
        for (int mi = 0; mi < 2; mi++) {
            const float4 ahv = base[wks * 64 + mi * 32 + lane];
            const float4 alv = base[256 + wks * 64 + mi * 32 + lane];
            uint32_t ahi[4] = {__float_as_uint(ahv.x), __float_as_uint(ahv.y),
                               __float_as_uint(ahv.z), __float_as_uint(ahv.w)};
            uint32_t alo[4] = {__float_as_uint(alv.x), __float_as_uint(alv.y),
                               __float_as_uint(alv.z), __float_as_uint(alv.w)};
            mma_tf32(acc[mi][0], ahi, bh0, bh1);
            mma_tf32(acc[mi][1], ahi, bh2, bh3);
            mma_tf32(acc[mi][0], ahi, bl0, bl1);
            mma_tf32(acc[mi][1], ahi, bl2, bl3);
            mma_tf32(acc[mi][0], alo, bh0, bh1);
            mma_tf32(acc[mi][1], alo, bh2, bh3);
        }

        s = (s + 1) % 3;
    }

    // ---- split-K reduction via smem (pool[0..1023]) ----
    __syncthreads();
    float4* red = pool;
#pragma unroll
    for (int mi = 0; mi < 2; mi++)
#pragma unroll
        for (int nfl = 0; nfl < 2; nfl++)
            red[wid * 128 + (mi * 2 + nfl) * 32 + lane] =
                make_float4(acc[mi][nfl][0], acc[mi][nfl][1], acc[mi][nfl][2], acc[mi][nfl][3]);
    __syncthreads();

    // every warp is a reducer: (mi = wid&1, nfg = wid>>1)
    const int mi = wid & 1;
    const int nfg = wid >> 1;
    const int nfp = nfg >> 1;
    const int nfl = nfg & 1;
    const int set = mi * 2 + nfl;
    float4 s0 = red[(nfp * 4 + 0) * 128 + set * 32 + lane];
    const float4 s1 = red[(nfp * 4 + 1) * 128 + set * 32 + lane];
    const float4 s2 = red[(nfp * 4 + 2) * 128 + set * 32 + lane];
    const float4 s3 = red[(nfp * 4 + 3) * 128 + set * 32 + lane];
    float v[4];
    v[0] = (s0.x + s1.x) + (s2.x + s3.x);
    v[1] = (s0.y + s1.y) + (s2.y + s3.y);
    v[2] = (s0.z + s1.z) + (s2.z + s3.z);
    v[3] = (s0.w + s1.w) + (s2.w + s3.w);

    const int col = bn + nfg * 8 + 2 * tg;
    const float b0v = bias[col];
    const float b1v = bias[col + 1];
    v[0] += b0v; v[1] += b1v; v[2] += b0v; v[3] += b1v;
    if (RELU) {
#pragma unroll
        for (int e = 0; e < 4; e++) v[e] = fmaxf(v[e], 0.f);
    }

    if (FRAGOUT) {
        // stage decomposed values in fragment order, then contiguous copy out
        float* stHi = reinterpret_cast<float*>(pool + 1024);   // 256 f4
        float* stLo = stHi + 1024;                             // 256 f4
#pragma unroll
        for (int e = 0; e < 4; e++) {
            const int cc = 2 * tg + (e & 1);                   // col offset in n8
            const int lane_c = g * 4 + (cc & 3);
            const int comp = (e >> 1) + 2 * (cc >> 2);
            const int su = nfg * 64 + mi * 32 + lane_c;
            const float hi = __uint_as_float(f32_to_tf32(v[e]));
            stHi[su * 4 + comp] = hi;
            stLo[su * 4 + comp] = __uint_as_float(f32_to_tf32(v[e] - hi));
        }
        __syncthreads();
        const size_t dst = (size_t)(mb * 8 + blockIdx.x) * 256 + tid;
        reinterpret_cast<float4*>(oHi)[dst] = reinterpret_cast<float4*>(stHi)[tid];
        reinterpret_cast<float4*>(oLo)[dst] = reinterpret_cast<float4*>(stLo)[tid];
    } else {
        const int row0 = mb * 32 + mi * 16 + g;
        *reinterpret_cast<float2*>(&Cplain[(size_t)row0 * N + col]) = make_float2(v[0], v[1]);
        *reinterpret_cast<float2*>(&Cplain[(size_t)(row0 + 8) * N + col]) = make_float2(v[2], v[3]);
    }
}

// ---------------------------------------------------------------------------
// Patch gather + dot + indices. One block (256 threads) per query.
// Output layout in d_out (float32):
//   [0, N*49)        logits (n, py, px)
//   [N*49, N*49*5)   indices as float (n, py, px, {b,y,x,q})
// ---------------------------------------------------------------------------
__global__ void __launch_bounds__(256)
patch_kernel(const float* __restrict__ fm, const float* __restrict__ qe,
             const float* __restrict__ qpos, const int* __restrict__ shapes,
             float* __restrict__ out, int N, int Q, int D) {
    __shared__ float sq[256];
    const int n = blockIdx.x;
    if (n >= N) return;

    const int b = n / Q;
    const int q = n - b * Q;
    const int Hb = shapes[2 * b + 0];
    const int Wb = shapes[2 * b + 1];

    const float posx = qpos[2 * n + 0];
    const float posy = qpos[2 * n + 1];
    const int cy = (int)(posy * (float)Hb);
    const int cx = (int)(posx * (float)Wb);

    for (int d = threadIdx.x; d < D; d += blockDim.x)
        sq[d] = qe[(size_t)n * D + d];
    __syncthreads();

    const int warp = threadIdx.x >> 5;
    const int lane = threadIdx.x & 31;
    const float4* sq4 = reinterpret_cast<const float4*>(sq);
    const float4 q0 = sq4[lane];
    const float4 q1 = sq4[lane + 32];

    float* out_logits = out;
    float* out_idx = out + (size_t)N * PP;

    for (int p = warp; p < PP; p += 8) {
        const int dy = p / PATCH - PATCH / 2;
        const int dx = p % PATCH - PATCH / 2;
        int y = cy + dy;
        int x = cx + dx;
        y = min(max(y, 0), Hb - 1);
        x = min(max(x, 0), Wb - 1);

        const size_t row_off = (((size_t)b * Hb + y) * Wb + x) * (size_t)D;
        const float4* row = reinterpret_cast<const float4*>(fm + row_off);

        const float4 f0 = row[lane];
        const float4 f1 = row[lane + 32];

        float s = f0.x * q0.x + f0.y * q0.y + f0.z * q0.z + f0.w * q0.w;
        s = fmaf(f1.x, q1.x, s);
        s = fmaf(f1.y, q1.y, s);
        s = fmaf(f1.z, q1.z, s);
        s = fmaf(f1.w, q1.w, s);

#pragma unroll
        for (int off = 16; off; off >>= 1)
            s += __shfl_xor_sync(0xFFFFFFFFu, s, off);

        if (lane == 0) {
            out_logits[(size_t)n * PP + p] = s;
            float4 iv = make_float4((float)b, (float)y, (float)x, (float)q);
            *reinterpret_cast<float4*>(&out_idx[((size_t)n * PP + p) * 4]) = iv;
        }
    }
}

extern "C" void kernel_launch(void* const* d_in, const int* in_sizes, int n_in,
                              void* d_out, int out_size) {
    const float* fm      = (const float*)d_in[0];
    const float* queries = (const float*)d_in[1];
    const float* qpos    = (const float*)d_in[2];
    const int*   shapes  = (const int*)d_in[4];
    const float* W0 = (const float*)d_in[5];
    const float* b0 = (const float*)d_in[6];
    const float* W1 = (const float*)d_in[7];
    const float* b1 = (const float*)d_in[8];
    const float* W2 = (const float*)d_in[9];
    const float* b2 = (const float*)d_in[10];
    const float* W3 = (const float*)d_in[11];
    const float* b3 = (const float*)d_in[12];

    const int B = in_sizes[3];               // query_batch_offsets length
    const int D = in_sizes[6];               // bias length (256)
    const int N = in_sizes[1] / D;           // total queries (1024)
    const int Q = N / B;
    const int LSZ = 8 * 4096 * 4;            // floats per layer in Wf

    float *fhA, *flA, *fhB, *flB, *act, *wf;
    cudaGetSymbolAddress((void**)&fhA, g_fhA);
    cudaGetSymbolAddress((void**)&flA, g_flA);
    cudaGetSymbolAddress((void**)&fhB, g_fhB);
    cudaGetSymbolAddress((void**)&flB, g_flB);
    cudaGetSymbolAddress((void**)&act, g_act);
    cudaGetSymbolAddress((void**)&wf, g_wf);

    prep_kernel<<<512, 256>>>(W0, W1, W2, W3, queries, wf, fhA, flA, D);

    dim3 gblock(256);
    dim3 ggrid(D / 32, N / 32);              // (8, 32) = 256 blocks

    gemm_tf32_kernel<true,  true ><<<ggrid, gblock>>>(fhA, flA, wf + 0 * LSZ, b0, fhB, flB, nullptr, N, D, D);
    gemm_tf32_kernel<true,  true ><<<ggrid, gblock>>>(fhB, flB, wf + 1 * LSZ, b1, fhA, flA, nullptr, N, D, D);
    gemm_tf32_kernel<true,  true ><<<ggrid, gblock>>>(fhA, flA, wf + 2 * LSZ, b2, fhB, flB, nullptr, N, D, D);
    gemm_tf32_kernel<false, false><<<ggrid, gblock>>>(fhB, flB, wf + 3 * LSZ, b3, nullptr, nullptr, act, N, D, D);

    patch_kernel<<<N, 256>>>(fm, act, qpos, shapes, (float*)d_out, N, Q, D);
}